// round 1
// baseline (speedup 1.0000x reference)
#include <cuda_runtime.h>

// Problem constants
#define NQ 16384            // 16 * 1024 queries
#define NC 8192             // codebook size
#define CD 256              // code dim
#define BM 128              // queries per block
#define BN 64               // codes per tile
#define NTILES (NC / BN)    // 128
#define NBLK (NQ / BM)      // 128
#define QSTRIDE 260         // padded Q smem row stride (floats), multiple of 4

// Scratch (no allocations allowed -> __device__ globals)
__device__ float g_ET[NC * CD];   // E transposed per 64-code tile, k-major, XOR-swizzled (8 MB)
__device__ float g_esq[NC];       // ||e||^2 per code
__device__ int   g_argmin[NQ];    // argmin index per query
__device__ float g_loss;          // sum of squared diffs

// ---------------------------------------------------------------------------
// Kernel A: per-code e_sq + build swizzled k-major E_T + zero loss accumulator
// ---------------------------------------------------------------------------
__global__ void prep_kernel(const float* __restrict__ E) {
    int c = blockIdx.x * blockDim.x + threadIdx.x;   // 0..8191
    if (c == 0) g_loss = 0.0f;
    if (c >= NC) return;

    const float4* e4 = (const float4*)(E + (size_t)c * CD);
    int tile = c >> 6;
    int cl = c & 63;
    int g = cl >> 2;       // 16-byte group within 64-code row
    int m = cl & 3;
    float* dst = g_ET + (size_t)tile * (BN * CD);

    float s = 0.0f;
    #pragma unroll 4
    for (int kc = 0; kc < CD / 4; ++kc) {
        float4 v = e4[kc];
        s += v.x * v.x; s += v.y * v.y; s += v.z * v.z; s += v.w * v.w;
        int k0 = kc * 4;
        dst[(k0 + 0) * BN + ((g ^ ((k0 + 0) & 15)) << 2) + m] = v.x;
        dst[(k0 + 1) * BN + ((g ^ ((k0 + 1) & 15)) << 2) + m] = v.y;
        dst[(k0 + 2) * BN + ((g ^ ((k0 + 2) & 15)) << 2) + m] = v.z;
        dst[(k0 + 3) * BN + ((g ^ ((k0 + 3) & 15)) << 2) + m] = v.w;
    }
    g_esq[c] = s;
}

// ---------------------------------------------------------------------------
// Kernel B: fused SGEMM + argmin.  score = (q_sq + e_sq) - 2*dot
// ---------------------------------------------------------------------------
__global__ void __launch_bounds__(256, 1) argmin_kernel(const float* __restrict__ Q) {
    extern __shared__ float sm[];
    float* Qs  = sm;                          // BM * QSTRIDE floats (row-major, padded)
    float* Es  = sm + BM * QSTRIDE;           // BN * CD floats (k-major swizzled); reused for reduction
    float* qsq = Es + BN * CD;                // BM floats

    int tid = threadIdx.x;
    int tx = tid & 15;        // code group (4 codes)
    int ty = tid >> 4;        // query group (8 queries)
    int r0 = ty * 8;

    // Stage Q tile (coalesced loads, conflict-free float4 smem stores)
    const float4* q4 = (const float4*)(Q + (size_t)blockIdx.x * BM * CD);
    for (int i = tid; i < BM * (CD / 4); i += 256) {
        int row = i >> 6;
        int kc = i & 63;
        ((float4*)(Qs + row * QSTRIDE))[kc] = q4[row * (CD / 4) + kc];
    }
    __syncthreads();

    // q_sq per row
    if (tid < BM) {
        const float* r = Qs + tid * QSTRIDE;
        float s = 0.0f;
        #pragma unroll 8
        for (int k = 0; k < CD; ++k) s += r[k] * r[k];
        qsq[tid] = s;
    }
    __syncthreads();

    float myqsq[8];
    #pragma unroll
    for (int i = 0; i < 8; ++i) myqsq[i] = qsq[r0 + i];

    float bestv[8];
    int   besti[8];
    #pragma unroll
    for (int i = 0; i < 8; ++i) { bestv[i] = 3.4e38f; besti[i] = 0; }

    for (int t = 0; t < NTILES; ++t) {
        __syncthreads();   // protect Es before overwrite
        {
            const float4* src = (const float4*)(g_ET + (size_t)t * (BN * CD));
            float4* dstE = (float4*)Es;
            #pragma unroll 4
            for (int i = tid; i < BN * CD / 4; i += 256) dstE[i] = src[i];
        }
        __syncthreads();

        float4 esq4 = ((const float4*)(g_esq + t * BN))[tx];

        float acc[8][4];
        #pragma unroll
        for (int i = 0; i < 8; ++i)
            #pragma unroll
            for (int j = 0; j < 4; ++j) acc[i][j] = 0.0f;

        #pragma unroll 2
        for (int k4 = 0; k4 < CD / 4; ++k4) {
            int k = k4 * 4;
            float b[4][4];
            #pragma unroll
            for (int kk = 0; kk < 4; ++kk) {
                float4 bv = ((const float4*)(Es + (k + kk) * BN))[tx ^ ((k + kk) & 15)];
                b[kk][0] = bv.x; b[kk][1] = bv.y; b[kk][2] = bv.z; b[kk][3] = bv.w;
            }
            #pragma unroll
            for (int i = 0; i < 8; ++i) {
                const float* qr = Qs + (r0 + i) * QSTRIDE + k;
                float a0 = qr[0], a1 = qr[1], a2 = qr[2], a3 = qr[3];
                #pragma unroll
                for (int j = 0; j < 4; ++j) {
                    acc[i][j] += a0 * b[0][j];
                    acc[i][j] += a1 * b[1][j];
                    acc[i][j] += a2 * b[2][j];
                    acc[i][j] += a3 * b[3][j];
                }
            }
        }

        float eq[4] = {esq4.x, esq4.y, esq4.z, esq4.w};
        int base_idx = t * BN + tx * 4;
        #pragma unroll
        for (int i = 0; i < 8; ++i) {
            #pragma unroll
            for (int j = 0; j < 4; ++j) {
                float s = (myqsq[i] + eq[j]) - 2.0f * acc[i][j];
                if (s < bestv[i]) { bestv[i] = s; besti[i] = base_idx + j; }
            }
        }
    }

    // Cross-tx reduction (reuse Es region)
    __syncthreads();
    float* redv = Es;                      // BM*16 floats
    int*   redi = (int*)(Es + BM * 16);    // BM*16 ints
    #pragma unroll
    for (int i = 0; i < 8; ++i) {
        redv[(r0 + i) * 16 + tx] = bestv[i];
        redi[(r0 + i) * 16 + tx] = besti[i];
    }
    __syncthreads();
    if (tid < BM) {
        float bv = redv[tid * 16];
        int bi = redi[tid * 16];
        #pragma unroll
        for (int j = 1; j < 16; ++j) {
            float v = redv[tid * 16 + j];
            int ii = redi[tid * 16 + j];
            if (v < bv || (v == bv && ii < bi)) { bv = v; bi = ii; }
        }
        g_argmin[blockIdx.x * BM + tid] = bi;
    }
}

// ---------------------------------------------------------------------------
// Kernel C: gather quantized (straight-through value) + index output + loss sum
// ---------------------------------------------------------------------------
__global__ void gather_kernel(const float* __restrict__ Q, const float* __restrict__ E,
                              float* __restrict__ out) {
    int q = blockIdx.x * 4 + (threadIdx.x >> 6);
    int lane = threadIdx.x & 63;
    int idx = g_argmin[q];

    float4 qv = ((const float4*)Q)[q * (CD / 4) + lane];
    float4 ev = ((const float4*)E)[(size_t)idx * (CD / 4) + lane];

    float dx = ev.x - qv.x, dy = ev.y - qv.y, dz = ev.z - qv.z, dw = ev.w - qv.w;
    float4 o;
    o.x = qv.x + dx; o.y = qv.y + dy; o.z = qv.z + dz; o.w = qv.w + dw;
    ((float4*)(out + NQ))[q * (CD / 4) + lane] = o;
    if (lane == 0) out[q] = (float)idx;

    float d2 = dx * dx + dy * dy + dz * dz + dw * dw;
    #pragma unroll
    for (int off = 16; off > 0; off >>= 1)
        d2 += __shfl_down_sync(0xffffffffu, d2, off);

    __shared__ float ws[8];
    int w = threadIdx.x >> 5;
    if ((threadIdx.x & 31) == 0) ws[w] = d2;
    __syncthreads();
    if (threadIdx.x == 0) {
        float s = 0.0f;
        #pragma unroll
        for (int i = 0; i < 8; ++i) s += ws[i];
        atomicAdd(&g_loss, s);
    }
}

// ---------------------------------------------------------------------------
// Kernel D: finalize vq_loss = codebook + 0.25*commit = 1.25 * MSE
// ---------------------------------------------------------------------------
__global__ void loss_kernel(float* __restrict__ out) {
    out[NQ + NQ * CD] = 1.25f * g_loss * (1.0f / (float)(NQ * CD));
}

// ---------------------------------------------------------------------------
extern "C" void kernel_launch(void* const* d_in, const int* in_sizes, int n_in,
                              void* d_out, int out_size) {
    const float* Q = (const float*)d_in[0];
    const float* E = (const float*)d_in[1];
    // Defensive: detect swapped input order via element counts
    if (n_in >= 2 && in_sizes[0] == NC * CD && in_sizes[1] == NQ * CD) {
        const float* t = Q; Q = E; E = t;
    }
    float* out = (float*)d_out;

    const int smem_bytes = (BM * QSTRIDE + BN * CD + BM) * 4;   // 199,168 B
    cudaFuncSetAttribute(argmin_kernel, cudaFuncAttributeMaxDynamicSharedMemorySize, smem_bytes);

    prep_kernel<<<NC / 256, 256>>>(E);
    argmin_kernel<<<NBLK, 256, smem_bytes>>>(Q);
    gather_kernel<<<NQ / 4, 256>>>(Q, E, out);
    loss_kernel<<<1, 1>>>(out);
}

// round 10
// speedup vs baseline: 1.0868x; 1.0868x over previous
#include <cuda_runtime.h>
#include <cuda_bf16.h>
#include <cstdint>

#define NQ 16384
#define NC 8192
#define CD 256
#define BM 128
#define BN 128
#define NTILES (NC / BN)      // 64
#define NBLK (NQ / BM)        // 128
#define NKC 8                 // k-chunks of 32 per 256
#define NIT (NTILES * NKC)    // 512

// ---- device scratch: tf32 2-term splits stored as fp32 ----
__device__ float g_Qh[NQ * CD];
__device__ float g_Ql[NQ * CD];
__device__ float g_Eh[NC * CD];
__device__ float g_El[NC * CD];
__device__ float g_qsq[NQ];
__device__ float g_esq[NC];
__device__ int   g_cand1[NQ];
__device__ int   g_cand2[NQ];
__device__ int   g_argmin[NQ];
__device__ float g_loss;

// ---- SMEM: per buffer [Qh|Ql|Eh|El], each 128 rows x RSTRIDE floats ----
#define RSTRIDE 36                    // 32 data + 4 pad; 36 mod 32 = 4 -> 4g+tc conflict-free
#define TERM_F  4608                  // 128*36 floats per term
#define BUF_F   18432                 // 4 terms
#define SM_TOTAL 147456               // 2 bufs * 73728 B

__device__ __forceinline__ uint32_t smem_u32(const void* p) {
    uint32_t a;
    asm("{ .reg .u64 t; cvta.to.shared.u64 t, %1; cvt.u32.u64 %0, t; }" : "=r"(a) : "l"(p));
    return a;
}
__device__ __forceinline__ void cp16(uint32_t dst, const void* src) {
    asm volatile("cp.async.cg.shared.global [%0], [%1], 16;" :: "r"(dst), "l"(src) : "memory");
}
#define CP_COMMIT() asm volatile("cp.async.commit_group;" ::: "memory")
#define CP_WAIT(N)  asm volatile("cp.async.wait_group %0;" :: "n"(N) : "memory")

__device__ __forceinline__ float tf32r(float x) {
    unsigned u;
    asm("cvt.rna.tf32.f32 %0, %1;" : "=r"(u) : "f"(x));
    return __uint_as_float(u);
}

__device__ __forceinline__ void mma_tf32(float* c, const uint32_t* a, uint32_t b0, uint32_t b1) {
    asm volatile(
        "mma.sync.aligned.m16n8k8.row.col.f32.tf32.tf32.f32 "
        "{%0,%1,%2,%3}, {%4,%5,%6,%7}, {%8,%9}, {%0,%1,%2,%3};"
        : "+f"(c[0]), "+f"(c[1]), "+f"(c[2]), "+f"(c[3])
        : "r"(a[0]), "r"(a[1]), "r"(a[2]), "r"(a[3]), "r"(b0), "r"(b1));
}

// top-2 insert with (value, index) lexicographic ordering
__device__ __forceinline__ void ins2(float v, int i, float& v1, int& i1, float& v2, int& i2) {
    if (v < v2 || (v == v2 && i < i2)) {
        if (v < v1 || (v == v1 && i < i1)) { v2 = v1; i2 = i1; v1 = v; i1 = i; }
        else { v2 = v; i2 = i; }
    }
}

// ---------------------------------------------------------------------------
// Kernel A: tf32 two-term split (row-major) + qsq/esq.  One warp per row.
// ---------------------------------------------------------------------------
__global__ void prep_kernel(const float* __restrict__ Q, const float* __restrict__ E) {
    int gw = blockIdx.x * 8 + (threadIdx.x >> 5);
    int lane = threadIdx.x & 31;
    if (blockIdx.x == 0 && threadIdx.x == 0) g_loss = 0.0f;
    if (gw >= NC + NQ) return;

    const float4* src;
    float4 *d1, *d2;
    if (gw < NC) {
        src = (const float4*)(E + (size_t)gw * CD);
        d1 = (float4*)(g_Eh + (size_t)gw * CD);
        d2 = (float4*)(g_El + (size_t)gw * CD);
    } else {
        int q = gw - NC;
        src = (const float4*)(Q + (size_t)q * CD);
        d1 = (float4*)(g_Qh + (size_t)q * CD);
        d2 = (float4*)(g_Ql + (size_t)q * CD);
    }

    float s = 0.0f;
    #pragma unroll
    for (int half = 0; half < 2; ++half) {
        int i = lane + half * 32;
        float4 v = src[i];
        float vv[4] = {v.x, v.y, v.z, v.w};
        float4 hi, lo;
        float hv[4], lv[4];
        #pragma unroll
        for (int u = 0; u < 4; ++u) {
            s += vv[u] * vv[u];
            hv[u] = tf32r(vv[u]);
            lv[u] = tf32r(vv[u] - hv[u]);
        }
        hi.x = hv[0]; hi.y = hv[1]; hi.z = hv[2]; hi.w = hv[3];
        lo.x = lv[0]; lo.y = lv[1]; lo.z = lv[2]; lo.w = lv[3];
        d1[i] = hi;
        d2[i] = lo;
    }
    #pragma unroll
    for (int off = 16; off > 0; off >>= 1)
        s += __shfl_xor_sync(0xffffffffu, s, off);
    if (lane == 0) {
        if (gw < NC) g_esq[gw] = s;
        else         g_qsq[gw - NC] = s;
    }
}

// ---------------------------------------------------------------------------
// Kernel B: 3xTF32 mma.sync GEMM + fused top-2 argmin
// Fragment layout per CUTLASS SM80_16x8x8_F32TF32TF32F32_TN:
//   A: a0=(g,tc) a1=(g+8,tc) a2=(g,tc+4) a3=(g+8,tc+4)
//   B: b0=(n=g,k=tc) b1=(n=g,k=tc+4)
//   C: c0/c1=(g, 2tc/2tc+1) c2/c3=(g+8, 2tc/2tc+1)
// ---------------------------------------------------------------------------
__global__ void __launch_bounds__(256, 1) argmin_mma_kernel() {
    extern __shared__ float smf[];
    uint32_t base = smem_u32(smf);
    int tid = threadIdx.x;
    int lane = tid & 31;
    int wm = (tid >> 5) & 3;      // warp M (32 rows)
    int wn = tid >> 7;            // warp N (64 cols)
    int g = lane >> 2;            // groupID
    int tc = lane & 3;            // threadID_in_group
    int mb = blockIdx.x;

    const float* garr[4] = {g_Qh, g_Ql, g_Eh, g_El};

    // prologue: stage chunk 0 into buffer 0
    {
        #pragma unroll
        for (int j = 0; j < 16; ++j) {
            int idx = j * 256 + tid;
            int arr = idx >> 10, r = (idx >> 3) & 127, sg = idx & 7;
            int row = (arr < 2 ? mb : 0) * 128 + r;
            const float* src = garr[arr] + (size_t)row * CD + sg * 4;
            cp16(base + arr * (TERM_F * 4) + r * (RSTRIDE * 4) + sg * 16, src);
        }
        CP_COMMIT();
    }

    float qsq_r[4];
    #pragma unroll
    for (int s = 0; s < 4; ++s)
        qsq_r[s] = __ldg(g_qsq + mb * 128 + wm * 32 + g + s * 8);

    float acc[2][8][4];
    #pragma unroll
    for (int mf = 0; mf < 2; ++mf)
        #pragma unroll
        for (int nf = 0; nf < 8; ++nf)
            #pragma unroll
            for (int u = 0; u < 4; ++u) acc[mf][nf][u] = 0.0f;

    float bv1[4], bv2[4];
    int   bi1[4], bi2[4];
    #pragma unroll
    for (int s = 0; s < 4; ++s) {
        bv1[s] = 3.4e38f; bi1[s] = 0x7FFFFFFF;
        bv2[s] = 3.4e38f; bi2[s] = 0x7FFFFFFF;
    }

    int cn_base = wn * 64 + 2 * tc;
    int aoff = (wm * 32 + g) * RSTRIDE + tc;                 // A base (col tc)
    int boff = (wn * 64 + g) * RSTRIDE + tc + 2 * TERM_F;    // B base (k col tc)

    for (int it = 0; it < NIT; ++it) {
        int t = it >> 3, kc = it & 7, buf = it & 1;

        if (it < NIT - 1) {
            int nit = it + 1, tn = nit >> 3, kcn = nit & 7, bufn = nit & 1;
            #pragma unroll
            for (int j = 0; j < 16; ++j) {
                int idx = j * 256 + tid;
                int arr = idx >> 10, r = (idx >> 3) & 127, sg = idx & 7;
                int row = (arr < 2 ? mb : tn) * 128 + r;
                const float* src = garr[arr] + (size_t)row * CD + kcn * 32 + sg * 4;
                cp16(base + bufn * (BUF_F * 4) + arr * (TERM_F * 4) + r * (RSTRIDE * 4) + sg * 16,
                     src);
            }
            CP_COMMIT();
            CP_WAIT(1);
        } else {
            CP_WAIT(0);
        }
        __syncthreads();

        const float* B = smf + buf * BUF_F;
        #pragma unroll
        for (int ks = 0; ks < 4; ++ks) {
            int kb = ks * 8;
            uint32_t ah[2][4], al[2][4];
            #pragma unroll
            for (int mf = 0; mf < 2; ++mf) {
                int qi = aoff + mf * (16 * RSTRIDE) + kb;
                ah[mf][0] = __float_as_uint(B[qi]);
                ah[mf][1] = __float_as_uint(B[qi + 8 * RSTRIDE]);
                ah[mf][2] = __float_as_uint(B[qi + 4]);
                ah[mf][3] = __float_as_uint(B[qi + 8 * RSTRIDE + 4]);
                al[mf][0] = __float_as_uint(B[qi + TERM_F]);
                al[mf][1] = __float_as_uint(B[qi + TERM_F + 8 * RSTRIDE]);
                al[mf][2] = __float_as_uint(B[qi + TERM_F + 4]);
                al[mf][3] = __float_as_uint(B[qi + TERM_F + 8 * RSTRIDE + 4]);
            }
            uint32_t bh[8][2], bl[8][2];
            #pragma unroll
            for (int nf = 0; nf < 8; ++nf) {
                int ei = boff + nf * (8 * RSTRIDE) + kb;
                bh[nf][0] = __float_as_uint(B[ei]);
                bh[nf][1] = __float_as_uint(B[ei + 4]);
                bl[nf][0] = __float_as_uint(B[ei + TERM_F]);
                bl[nf][1] = __float_as_uint(B[ei + TERM_F + 4]);
            }
            #pragma unroll
            for (int mf = 0; mf < 2; ++mf) {
                #pragma unroll
                for (int nf = 0; nf < 8; ++nf) {
                    mma_tf32(acc[mf][nf], ah[mf], bh[nf][0], bh[nf][1]);  // hi*hi
                    mma_tf32(acc[mf][nf], ah[mf], bl[nf][0], bl[nf][1]);  // hi*lo
                    mma_tf32(acc[mf][nf], al[mf], bh[nf][0], bh[nf][1]);  // lo*hi
                }
            }
        }

        if (kc == 7) {
            #pragma unroll
            for (int nf = 0; nf < 8; ++nf) {
                int cn = cn_base + nf * 8;
                float2 eq = __ldg((const float2*)(g_esq + t * 128 + cn));
                #pragma unroll
                for (int mf = 0; mf < 2; ++mf) {
                    float* c = acc[mf][nf];
                    float s0 = (qsq_r[mf * 2]     + eq.x) - 2.0f * c[0];
                    float s1 = (qsq_r[mf * 2]     + eq.y) - 2.0f * c[1];
                    float s2 = (qsq_r[mf * 2 + 1] + eq.x) - 2.0f * c[2];
                    float s3 = (qsq_r[mf * 2 + 1] + eq.y) - 2.0f * c[3];
                    int gi = t * 128 + cn;
                    int r0 = mf * 2, r1 = mf * 2 + 1;
                    ins2(s0, gi,     bv1[r0], bi1[r0], bv2[r0], bi2[r0]);
                    ins2(s1, gi + 1, bv1[r0], bi1[r0], bv2[r0], bi2[r0]);
                    ins2(s2, gi,     bv1[r1], bi1[r1], bv2[r1], bi2[r1]);
                    ins2(s3, gi + 1, bv1[r1], bi1[r1], bv2[r1], bi2[r1]);
                    c[0] = 0.0f; c[1] = 0.0f; c[2] = 0.0f; c[3] = 0.0f;
                }
            }
        }
        __syncthreads();
    }

    // ---- cross-thread top-2 reduction (tc lanes hold disjoint columns) ----
    #pragma unroll
    for (int s = 0; s < 4; ++s) {
        #pragma unroll
        for (int off = 1; off <= 2; off <<= 1) {
            float ov1 = __shfl_xor_sync(0xffffffffu, bv1[s], off);
            int   oi1 = __shfl_xor_sync(0xffffffffu, bi1[s], off);
            float ov2 = __shfl_xor_sync(0xffffffffu, bv2[s], off);
            int   oi2 = __shfl_xor_sync(0xffffffffu, bi2[s], off);
            ins2(ov1, oi1, bv1[s], bi1[s], bv2[s], bi2[s]);
            ins2(ov2, oi2, bv1[s], bi1[s], bv2[s], bi2[s]);
        }
    }
    float* rv1 = smf;                 // [256]
    int*   ri1 = (int*)(smf + 256);
    float* rv2 = smf + 512;
    int*   ri2 = (int*)(smf + 768);
    if (tc == 0) {
        #pragma unroll
        for (int s = 0; s < 4; ++s) {
            int row = wm * 32 + g + s * 8;
            rv1[wn * 128 + row] = bv1[s];
            ri1[wn * 128 + row] = bi1[s];
            rv2[wn * 128 + row] = bv2[s];
            ri2[wn * 128 + row] = bi2[s];
        }
    }
    __syncthreads();
    if (tid < 128) {
        float v1 = rv1[tid];       int i1 = ri1[tid];
        float v2 = rv2[tid];       int i2 = ri2[tid];
        ins2(rv1[128 + tid], ri1[128 + tid], v1, i1, v2, i2);
        ins2(rv2[128 + tid], ri2[128 + tid], v1, i1, v2, i2);
        g_cand1[mb * 128 + tid] = i1;
        g_cand2[mb * 128 + tid] = i2;
    }
}

// ---------------------------------------------------------------------------
// Kernel B2: rescore top-2 with bit-exact R1 arithmetic (sequential fp32 FMA,
// ascending k) and pick the winner (strict <, lower index on tie).
// ---------------------------------------------------------------------------
__global__ void rescore_kernel(const float* __restrict__ Q, const float* __restrict__ E) {
    int q = blockIdx.x * 256 + threadIdx.x;
    int i1 = g_cand1[q], i2 = g_cand2[q];
    if (i2 < i1) { int t = i1; i1 = i2; i2 = t; }
    const float* qp = Q + (size_t)q * CD;
    const float* e1 = E + (size_t)i1 * CD;
    const float* e2 = E + (size_t)i2 * CD;
    float qsq = 0.0f, es1 = 0.0f, es2 = 0.0f, d1 = 0.0f, d2 = 0.0f;
    #pragma unroll 4
    for (int k = 0; k < CD; ++k) {
        float qk = qp[k];
        qsq = fmaf(qk, qk, qsq);
        float a = e1[k];
        es1 = fmaf(a, a, es1);
        d1  = fmaf(qk, a, d1);
        float b = e2[k];
        es2 = fmaf(b, b, es2);
        d2  = fmaf(qk, b, d2);
    }
    float s1 = (qsq + es1) - 2.0f * d1;
    float s2 = (qsq + es2) - 2.0f * d2;
    g_argmin[q] = (s2 < s1) ? i2 : i1;
}

// ---------------------------------------------------------------------------
// Kernel C: gather quantized + index output + loss sum
// ---------------------------------------------------------------------------
__global__ void gather_kernel(const float* __restrict__ Q, const float* __restrict__ E,
                              float* __restrict__ out) {
    int q = blockIdx.x * 4 + (threadIdx.x >> 6);
    int lane = threadIdx.x & 63;
    int idx = g_argmin[q];

    float4 qv = ((const float4*)Q)[q * (CD / 4) + lane];
    float4 ev = ((const float4*)E)[(size_t)idx * (CD / 4) + lane];

    float dx = ev.x - qv.x, dy = ev.y - qv.y, dz = ev.z - qv.z, dw = ev.w - qv.w;
    float4 o;
    o.x = qv.x + dx; o.y = qv.y + dy; o.z = qv.z + dz; o.w = qv.w + dw;
    ((float4*)(out + NQ))[q * (CD / 4) + lane] = o;
    if (lane == 0) out[q] = (float)idx;

    float d2 = dx * dx + dy * dy + dz * dz + dw * dw;
    #pragma unroll
    for (int off = 16; off > 0; off >>= 1)
        d2 += __shfl_down_sync(0xffffffffu, d2, off);

    __shared__ float ws[8];
    int w = threadIdx.x >> 5;
    if ((threadIdx.x & 31) == 0) ws[w] = d2;
    __syncthreads();
    if (threadIdx.x == 0) {
        float s = 0.0f;
        #pragma unroll
        for (int i = 0; i < 8; ++i) s += ws[i];
        atomicAdd(&g_loss, s);
    }
}

__global__ void loss_kernel(float* __restrict__ out) {
    out[NQ + NQ * CD] = 1.25f * g_loss * (1.0f / (float)(NQ * CD));
}

// ---------------------------------------------------------------------------
extern "C" void kernel_launch(void* const* d_in, const int* in_sizes, int n_in,
                              void* d_out, int out_size) {
    const float* Q = (const float*)d_in[0];
    const float* E = (const float*)d_in[1];
    if (n_in >= 2 && in_sizes[0] == NC * CD && in_sizes[1] == NQ * CD) {
        const float* t = Q; Q = E; E = t;
    }
    float* out = (float*)d_out;

    cudaFuncSetAttribute(argmin_mma_kernel, cudaFuncAttributeMaxDynamicSharedMemorySize,
                         SM_TOTAL);

    prep_kernel<<<(NC + NQ) / 8, 256>>>(Q, E);
    argmin_mma_kernel<<<NBLK, 256, SM_TOTAL>>>();
    rescore_kernel<<<NQ / 256, 256>>>(Q, E);
    gather_kernel<<<NQ / 4, 256>>>(Q, E, out);
    loss_kernel<<<1, 1>>>(out);
}

// round 11
// speedup vs baseline: 2.3248x; 2.1391x over previous
#include <cuda_runtime.h>
#include <cuda_bf16.h>
#include <cstdint>

#define NQ 16384
#define NC 8192
#define CD 256
#define BM 128
#define BN 128
#define NTILES (NC / BN)      // 64
#define NBLK (NQ / BM)        // 128

// ---- device scratch ----
__device__ __nv_bfloat16 g_Qh[NQ * CD];   // hi term, row-major [q][k]
__device__ __nv_bfloat16 g_Ql[NQ * CD];   // lo term
__device__ __nv_bfloat16 g_Eh[NC * CD];
__device__ __nv_bfloat16 g_El[NC * CD];
__device__ float g_qsq[NQ];
__device__ float g_esq[NC];
__device__ int   g_cand1[NQ];
__device__ int   g_cand2[NQ];
__device__ int   g_argmin[NQ];
__device__ float g_loss;

// ---- SMEM layout (bytes) ----
// Q: 2 terms x 128 rows x 528B (256 bf16 + 8 pad)  = 135168
// E: 2 bufs x 2 terms x 128 rows x 144B (64 bf16 + 8 pad) = 73728
#define QT_STRIDE 528
#define QT_BYTES  67584               // 128*528
#define ET_STRIDE 144
#define ET_BYTES  18432               // 128*144
#define EBUF_BYTES 36864              // 2 terms
#define SM_E      135168
#define SM_TOTAL  208896

__device__ __forceinline__ uint32_t smem_u32(const void* p) {
    uint32_t a;
    asm("{ .reg .u64 t; cvta.to.shared.u64 t, %1; cvt.u32.u64 %0, t; }" : "=r"(a) : "l"(p));
    return a;
}

__device__ __forceinline__ void cp16(uint32_t dst, const void* src) {
    asm volatile("cp.async.cg.shared.global [%0], [%1], 16;" :: "r"(dst), "l"(src) : "memory");
}
#define CP_COMMIT() asm volatile("cp.async.commit_group;" ::: "memory")
#define CP_WAIT(N)  asm volatile("cp.async.wait_group %0;" :: "n"(N) : "memory")

__device__ __forceinline__ void ldsm4(uint32_t* r, uint32_t addr) {
    asm volatile("ldmatrix.sync.aligned.m8n8.x4.shared.b16 {%0,%1,%2,%3}, [%4];"
                 : "=r"(r[0]), "=r"(r[1]), "=r"(r[2]), "=r"(r[3]) : "r"(addr));
}

__device__ __forceinline__ void mma16816(float* c, const uint32_t* a, uint32_t b0, uint32_t b1) {
    asm volatile(
        "mma.sync.aligned.m16n8k16.row.col.f32.bf16.bf16.f32 "
        "{%0,%1,%2,%3}, {%4,%5,%6,%7}, {%8,%9}, {%0,%1,%2,%3};"
        : "+f"(c[0]), "+f"(c[1]), "+f"(c[2]), "+f"(c[3])
        : "r"(a[0]), "r"(a[1]), "r"(a[2]), "r"(a[3]), "r"(b0), "r"(b1));
}

// top-2 insert with (value, index) lexicographic ordering
__device__ __forceinline__ void ins2(float v, int i, float& v1, int& i1, float& v2, int& i2) {
    if (v < v2 || (v == v2 && i < i2)) {
        if (v < v1 || (v == v1 && i < i1)) { v2 = v1; i2 = i1; v1 = v; i1 = i; }
        else { v2 = v; i2 = i; }
    }
}

// ---------------------------------------------------------------------------
// Kernel A: bf16 two-term split (row-major) + qsq/esq.  One thread per row.
// ---------------------------------------------------------------------------
__global__ void prep_kernel(const float* __restrict__ Q, const float* __restrict__ E) {
    int idx = blockIdx.x * blockDim.x + threadIdx.x;
    if (idx == 0) g_loss = 0.0f;
    if (idx >= NC + NQ) return;

    const float* src;
    __nv_bfloat16 *d1, *d2;
    if (idx < NC) { src = E + (size_t)idx * CD; d1 = g_Eh + (size_t)idx * CD; d2 = g_El + (size_t)idx * CD; }
    else { int q = idx - NC; src = Q + (size_t)q * CD; d1 = g_Qh + (size_t)q * CD; d2 = g_Ql + (size_t)q * CD; }

    float s = 0.0f;
    const float4* s4 = (const float4*)src;
    #pragma unroll 4
    for (int k4 = 0; k4 < CD / 4; ++k4) {
        float4 v = s4[k4];
        float vv[4] = {v.x, v.y, v.z, v.w};
        s += v.x * v.x + v.y * v.y + v.z * v.z + v.w * v.w;
        #pragma unroll
        for (int u = 0; u < 4; u += 2) {
            int k = k4 * 4 + u;
            float a = vv[u], b = vv[u + 1];
            __nv_bfloat16 ha = __float2bfloat16_rn(a);
            __nv_bfloat16 hb = __float2bfloat16_rn(b);
            __nv_bfloat16 la = __float2bfloat16_rn(a - __bfloat162float(ha));
            __nv_bfloat16 lb = __float2bfloat16_rn(b - __bfloat162float(hb));
            __nv_bfloat162 hi; hi.x = ha; hi.y = hb;
            __nv_bfloat162 lo; lo.x = la; lo.y = lb;
            *(__nv_bfloat162*)(d1 + k) = hi;
            *(__nv_bfloat162*)(d2 + k) = lo;
        }
    }
    if (idx < NC) g_esq[idx] = s;
    else          g_qsq[idx - NC] = s;
}

// ---------------------------------------------------------------------------
// Kernel B: mma.sync bf16 3-pass split GEMM + fused top-2 argmin
// (R5-proven fragment layout via ldmatrix; Q tile smem-resident)
// ---------------------------------------------------------------------------
__global__ void __launch_bounds__(256, 1) argmin_mma_kernel() {
    extern __shared__ char sm[];
    uint32_t base = smem_u32(sm);
    int tid = threadIdx.x;
    int lane = tid & 31;
    int wm = (tid >> 5) & 3;      // warp M position (32 rows)
    int wn = tid >> 7;            // warp N position (64 cols)
    int mb = blockIdx.x;

    // ---- stage Q tile (both terms) + first E chunk via cp.async ----
    {
        #pragma unroll
        for (int j = 0; j < 32; ++j) {
            int s = j * 256 + tid;
            int term = s >> 12;           // 4096 16B-segs per term
            int r = (s >> 5) & 127;
            int seg = s & 31;
            const __nv_bfloat16* src = (term ? g_Ql : g_Qh) + ((size_t)(mb * 128 + r) * CD + seg * 8);
            cp16(base + term * QT_BYTES + r * QT_STRIDE + seg * 16, src);
        }
        int term = tid >> 7, row = tid & 127;
        const __nv_bfloat16* src = (term ? g_El : g_Eh) + ((size_t)row * CD);
        uint32_t dst = base + SM_E + term * ET_BYTES + row * ET_STRIDE;
        #pragma unroll
        for (int sg = 0; sg < 8; ++sg) cp16(dst + sg * 16, (const char*)src + sg * 16);
        CP_COMMIT();
    }

    // per-thread row q_sq (rows wm*32 + g + {0,8,16,24})
    int g = lane >> 2;
    float qsq_r[4];
    #pragma unroll
    for (int s = 0; s < 4; ++s)
        qsq_r[s] = __ldg(g_qsq + mb * 128 + wm * 32 + g + s * 8);

    // ldmatrix base addresses
    uint32_t aQ = base + (uint32_t)(wm * 32 + (lane & 15)) * QT_STRIDE + ((lane >> 4) << 4);
    uint32_t bE0 = base + SM_E + (uint32_t)(wn * 64 + (lane & 15)) * ET_STRIDE + ((lane >> 4) << 4);

    float acc[2][8][4];
    #pragma unroll
    for (int mf = 0; mf < 2; ++mf)
        #pragma unroll
        for (int nf = 0; nf < 8; ++nf)
            #pragma unroll
            for (int u = 0; u < 4; ++u) acc[mf][nf][u] = 0.0f;

    float bv1[4], bv2[4];
    int   bi1[4], bi2[4];
    #pragma unroll
    for (int s = 0; s < 4; ++s) {
        bv1[s] = 3.4e38f; bi1[s] = 0x7FFFFFFF;
        bv2[s] = 3.4e38f; bi2[s] = 0x7FFFFFFF;
    }

    int cn_base = wn * 64 + 2 * (lane & 3);

    for (int it = 0; it < NTILES * 4; ++it) {
        int t = it >> 2, kc = it & 3, buf = it & 1;

        if (it < NTILES * 4 - 1) {
            int nit = it + 1, tn = nit >> 2, kcn = nit & 3, bufn = nit & 1;
            int term = tid >> 7, row = tid & 127;
            const __nv_bfloat16* src = (term ? g_El : g_Eh) +
                ((size_t)(tn * 128 + row) * CD + kcn * 64);
            uint32_t dst = base + SM_E + bufn * EBUF_BYTES + term * ET_BYTES + row * ET_STRIDE;
            #pragma unroll
            for (int sg = 0; sg < 8; ++sg) cp16(dst + sg * 16, (const char*)src + sg * 16);
            CP_COMMIT();
            CP_WAIT(1);
        } else {
            CP_WAIT(0);
        }
        __syncthreads();

        uint32_t bE = bE0 + buf * EBUF_BYTES;
        #pragma unroll
        for (int ks = 0; ks < 4; ++ks) {
            int kb = kc * 128 + ks * 32;
            uint32_t ah[2][4], al[2][4];
            ldsm4(ah[0], aQ + kb);
            ldsm4(ah[1], aQ + 16 * QT_STRIDE + kb);
            ldsm4(al[0], aQ + QT_BYTES + kb);
            ldsm4(al[1], aQ + QT_BYTES + 16 * QT_STRIDE + kb);
            uint32_t bh[4][4], bl[4][4];
            #pragma unroll
            for (int np = 0; np < 4; ++np) {
                ldsm4(bh[np], bE + np * 16 * ET_STRIDE + ks * 32);
                ldsm4(bl[np], bE + ET_BYTES + np * 16 * ET_STRIDE + ks * 32);
            }
            #pragma unroll
            for (int mf = 0; mf < 2; ++mf) {
                #pragma unroll
                for (int np = 0; np < 4; ++np) {
                    // pass 1: q_hi * e_hi
                    mma16816(acc[mf][np * 2],     ah[mf], bh[np][0], bh[np][2]);
                    mma16816(acc[mf][np * 2 + 1], ah[mf], bh[np][1], bh[np][3]);
                    // pass 2: q_hi * e_lo
                    mma16816(acc[mf][np * 2],     ah[mf], bl[np][0], bl[np][2]);
                    mma16816(acc[mf][np * 2 + 1], ah[mf], bl[np][1], bl[np][3]);
                    // pass 3: q_lo * e_hi
                    mma16816(acc[mf][np * 2],     al[mf], bh[np][0], bh[np][2]);
                    mma16816(acc[mf][np * 2 + 1], al[mf], bh[np][1], bh[np][3]);
                }
            }
        }

        if (kc == 3) {
            // per-tile epilogue: distances + running top-2, ascending col order
            #pragma unroll
            for (int nf = 0; nf < 8; ++nf) {
                int cn = cn_base + nf * 8;
                float2 eq = __ldg((const float2*)(g_esq + t * 128 + cn));
                #pragma unroll
                for (int mf = 0; mf < 2; ++mf) {
                    float* c = acc[mf][nf];
                    float s0 = (qsq_r[mf * 2]     + eq.x) - 2.0f * c[0];
                    float s1 = (qsq_r[mf * 2]     + eq.y) - 2.0f * c[1];
                    float s2 = (qsq_r[mf * 2 + 1] + eq.x) - 2.0f * c[2];
                    float s3 = (qsq_r[mf * 2 + 1] + eq.y) - 2.0f * c[3];
                    int gi = t * 128 + cn;
                    int r0 = mf * 2, r1 = mf * 2 + 1;
                    ins2(s0, gi,     bv1[r0], bi1[r0], bv2[r0], bi2[r0]);
                    ins2(s1, gi + 1, bv1[r0], bi1[r0], bv2[r0], bi2[r0]);
                    ins2(s2, gi,     bv1[r1], bi1[r1], bv2[r1], bi2[r1]);
                    ins2(s3, gi + 1, bv1[r1], bi1[r1], bv2[r1], bi2[r1]);
                    c[0] = 0.0f; c[1] = 0.0f; c[2] = 0.0f; c[3] = 0.0f;
                }
            }
        }
        __syncthreads();
    }

    // ---- cross-thread top-2 reduction ----
    #pragma unroll
    for (int s = 0; s < 4; ++s) {
        #pragma unroll
        for (int off = 1; off <= 2; off <<= 1) {
            float ov1 = __shfl_xor_sync(0xffffffffu, bv1[s], off);
            int   oi1 = __shfl_xor_sync(0xffffffffu, bi1[s], off);
            float ov2 = __shfl_xor_sync(0xffffffffu, bv2[s], off);
            int   oi2 = __shfl_xor_sync(0xffffffffu, bi2[s], off);
            ins2(ov1, oi1, bv1[s], bi1[s], bv2[s], bi2[s]);
            ins2(ov2, oi2, bv1[s], bi1[s], bv2[s], bi2[s]);
        }
    }
    float* rv1 = (float*)(sm + SM_E);          // [256]
    int*   ri1 = (int*)(sm + SM_E + 1024);
    float* rv2 = (float*)(sm + SM_E + 2048);
    int*   ri2 = (int*)(sm + SM_E + 3072);
    if ((lane & 3) == 0) {
        #pragma unroll
        for (int s = 0; s < 4; ++s) {
            int row = wm * 32 + g + s * 8;
            rv1[wn * 128 + row] = bv1[s];
            ri1[wn * 128 + row] = bi1[s];
            rv2[wn * 128 + row] = bv2[s];
            ri2[wn * 128 + row] = bi2[s];
        }
    }
    __syncthreads();
    if (tid < 128) {
        float v1 = rv1[tid];       int i1 = ri1[tid];
        float v2 = rv2[tid];       int i2 = ri2[tid];
        ins2(rv1[128 + tid], ri1[128 + tid], v1, i1, v2, i2);
        ins2(rv2[128 + tid], ri2[128 + tid], v1, i1, v2, i2);
        g_cand1[mb * 128 + tid] = i1;
        g_cand2[mb * 128 + tid] = i2;
    }
}

// ---------------------------------------------------------------------------
// Kernel B2: rescore top-2 with bit-exact sequential fp32 FMA (ascending k);
// strict <, lower index on tie.
// ---------------------------------------------------------------------------
__global__ void rescore_kernel(const float* __restrict__ Q, const float* __restrict__ E) {
    int q = blockIdx.x * 256 + threadIdx.x;
    int i1 = g_cand1[q], i2 = g_cand2[q];
    if (i2 < i1) { int t = i1; i1 = i2; i2 = t; }
    const float* qp = Q + (size_t)q * CD;
    const float* e1 = E + (size_t)i1 * CD;
    const float* e2 = E + (size_t)i2 * CD;
    float qsq = 0.0f, es1 = 0.0f, es2 = 0.0f, d1 = 0.0f, d2 = 0.0f;
    #pragma unroll 4
    for (int k = 0; k < CD; ++k) {
        float qk = qp[k];
        qsq = fmaf(qk, qk, qsq);
        float a = e1[k];
        es1 = fmaf(a, a, es1);
        d1  = fmaf(qk, a, d1);
        float b = e2[k];
        es2 = fmaf(b, b, es2);
        d2  = fmaf(qk, b, d2);
    }
    float s1 = (qsq + es1) - 2.0f * d1;
    float s2 = (qsq + es2) - 2.0f * d2;
    g_argmin[q] = (s2 < s1) ? i2 : i1;
}

// ---------------------------------------------------------------------------
// Kernel C: gather quantized + index output + loss sum
// ---------------------------------------------------------------------------
__global__ void gather_kernel(const float* __restrict__ Q, const float* __restrict__ E,
                              float* __restrict__ out) {
    int q = blockIdx.x * 4 + (threadIdx.x >> 6);
    int lane = threadIdx.x & 63;
    int idx = g_argmin[q];

    float4 qv = ((const float4*)Q)[q * (CD / 4) + lane];
    float4 ev = ((const float4*)E)[(size_t)idx * (CD / 4) + lane];

    float dx = ev.x - qv.x, dy = ev.y - qv.y, dz = ev.z - qv.z, dw = ev.w - qv.w;
    float4 o;
    o.x = qv.x + dx; o.y = qv.y + dy; o.z = qv.z + dz; o.w = qv.w + dw;
    ((float4*)(out + NQ))[q * (CD / 4) + lane] = o;
    if (lane == 0) out[q] = (float)idx;

    float d2 = dx * dx + dy * dy + dz * dz + dw * dw;
    #pragma unroll
    for (int off = 16; off > 0; off >>= 1)
        d2 += __shfl_down_sync(0xffffffffu, d2, off);

    __shared__ float ws[8];
    int w = threadIdx.x >> 5;
    if ((threadIdx.x & 31) == 0) ws[w] = d2;
    __syncthreads();
    if (threadIdx.x == 0) {
        float s = 0.0f;
        #pragma unroll
        for (int i = 0; i < 8; ++i) s += ws[i];
        atomicAdd(&g_loss, s);
    }
}

__global__ void loss_kernel(float* __restrict__ out) {
    out[NQ + NQ * CD] = 1.25f * g_loss * (1.0f / (float)(NQ * CD));
}

// ---------------------------------------------------------------------------
extern "C" void kernel_launch(void* const* d_in, const int* in_sizes, int n_in,
                              void* d_out, int out_size) {
    const float* Q = (const float*)d_in[0];
    const float* E = (const float*)d_in[1];
    if (n_in >= 2 && in_sizes[0] == NC * CD && in_sizes[1] == NQ * CD) {
        const float* t = Q; Q = E; E = t;
    }
    float* out = (float*)d_out;

    cudaFuncSetAttribute(argmin_mma_kernel, cudaFuncAttributeMaxDynamicSharedMemorySize,
                         SM_TOTAL);

    prep_kernel<<<(NC + NQ) / 256, 256>>>(Q, E);
    argmin_mma_kernel<<<NBLK, 256, SM_TOTAL>>>();
    rescore_kernel<<<NQ / 256, 256>>>(Q, E);
    gather_kernel<<<NQ / 4, 256>>>(Q, E, out);
    loss_kernel<<<1, 1>>>(out);
}

// round 13
// speedup vs baseline: 2.8154x; 1.2110x over previous
#include <cuda_runtime.h>
#include <cuda_fp16.h>
#include <cstdint>

#define NQ 16384
#define NC 8192
#define CD 256
#define BM 128
#define BN 128
#define NTILES (NC / BN)      // 64
#define NBLK (NQ / BM)        // 128

// ---- device scratch ----
__device__ __half g_Qh[NQ * CD];   // fp16 operands, row-major
__device__ __half g_Eh[NC * CD];
__device__ float g_qsq[NQ];
__device__ float g_esq[NC];
__device__ int4  g_cand[NQ];       // top-4 candidate indices per query
__device__ int   g_argmin[NQ];
__device__ float g_loss;

// ---- SMEM layout (bytes) ----
// Q: 128 rows x 528B (256 half + 8 pad) = 67584
// E: 2 bufs x 128 rows x 144B (64 half + 8 pad) = 36864
#define QT_STRIDE 528
#define ET_STRIDE 144
#define ET_BYTES  18432               // 128*144
#define SM_E      67584
#define SM_TOTAL  104448

__device__ __forceinline__ uint32_t smem_u32(const void* p) {
    uint32_t a;
    asm("{ .reg .u64 t; cvta.to.shared.u64 t, %1; cvt.u32.u64 %0, t; }" : "=r"(a) : "l"(p));
    return a;
}

__device__ __forceinline__ void cp16(uint32_t dst, const void* src) {
    asm volatile("cp.async.cg.shared.global [%0], [%1], 16;" :: "r"(dst), "l"(src) : "memory");
}
#define CP_COMMIT() asm volatile("cp.async.commit_group;" ::: "memory")
#define CP_WAIT(N)  asm volatile("cp.async.wait_group %0;" :: "n"(N) : "memory")

__device__ __forceinline__ void ldsm4(uint32_t* r, uint32_t addr) {
    asm volatile("ldmatrix.sync.aligned.m8n8.x4.shared.b16 {%0,%1,%2,%3}, [%4];"
                 : "=r"(r[0]), "=r"(r[1]), "=r"(r[2]), "=r"(r[3]) : "r"(addr));
}

__device__ __forceinline__ void mma16816(float* c, const uint32_t* a, uint32_t b0, uint32_t b1) {
    asm volatile(
        "mma.sync.aligned.m16n8k16.row.col.f32.f16.f16.f32 "
        "{%0,%1,%2,%3}, {%4,%5,%6,%7}, {%8,%9}, {%0,%1,%2,%3};"
        : "+f"(c[0]), "+f"(c[1]), "+f"(c[2]), "+f"(c[3])
        : "r"(a[0]), "r"(a[1]), "r"(a[2]), "r"(a[3]), "r"(b0), "r"(b1));
}

// sorted top-4 insert (ascending), (value,index) lexicographic
__device__ __forceinline__ void ins4(float v, int i, float* bv, int* bi) {
    if (v < bv[3] || (v == bv[3] && i < bi[3])) {
        if (v < bv[1] || (v == bv[1] && i < bi[1])) {
            bv[3] = bv[2]; bi[3] = bi[2]; bv[2] = bv[1]; bi[2] = bi[1];
            if (v < bv[0] || (v == bv[0] && i < bi[0])) {
                bv[1] = bv[0]; bi[1] = bi[0]; bv[0] = v; bi[0] = i;
            } else { bv[1] = v; bi[1] = i; }
        } else {
            if (v < bv[2] || (v == bv[2] && i < bi[2])) {
                bv[3] = bv[2]; bi[3] = bi[2]; bv[2] = v; bi[2] = i;
            } else { bv[3] = v; bi[3] = i; }
        }
    }
}

// ---------------------------------------------------------------------------
// Kernel A: fp16 convert (row-major) + fp32 qsq/esq.  One thread per row.
// ---------------------------------------------------------------------------
__global__ void prep_kernel(const float* __restrict__ Q, const float* __restrict__ E) {
    int idx = blockIdx.x * blockDim.x + threadIdx.x;
    if (idx == 0) g_loss = 0.0f;
    if (idx >= NC + NQ) return;

    const float* src;
    __half* d1;
    if (idx < NC) { src = E + (size_t)idx * CD; d1 = g_Eh + (size_t)idx * CD; }
    else { int q = idx - NC; src = Q + (size_t)q * CD; d1 = g_Qh + (size_t)q * CD; }

    float s = 0.0f;
    const float4* s4 = (const float4*)src;
    #pragma unroll 4
    for (int k4 = 0; k4 < CD / 4; ++k4) {
        float4 v = s4[k4];
        s += v.x * v.x + v.y * v.y + v.z * v.z + v.w * v.w;
        int k = k4 * 4;
        *(__half2*)(d1 + k)     = __floats2half2_rn(v.x, v.y);
        *(__half2*)(d1 + k + 2) = __floats2half2_rn(v.z, v.w);
    }
    if (idx < NC) g_esq[idx] = s;
    else          g_qsq[idx - NC] = s;
}

// ---------------------------------------------------------------------------
// Kernel B: single-pass fp16 mma.sync GEMM + fused top-4 candidate search
// ---------------------------------------------------------------------------
__global__ void __launch_bounds__(256, 1) argmin_mma_kernel() {
    extern __shared__ char sm[];
    uint32_t base = smem_u32(sm);
    int tid = threadIdx.x;
    int lane = tid & 31;
    int wm = (tid >> 5) & 3;      // warp M position (32 rows)
    int wn = tid >> 7;            // warp N position (64 cols)
    int mb = blockIdx.x;

    // ---- stage Q tile + first E chunk via cp.async ----
    {
        #pragma unroll
        for (int j = 0; j < 16; ++j) {
            int s = j * 256 + tid;          // 4096 16B segs
            int r = s >> 5;
            int seg = s & 31;
            const __half* src = g_Qh + ((size_t)(mb * 128 + r) * CD + seg * 8);
            cp16(base + r * QT_STRIDE + seg * 16, src);
        }
        // first E chunk: 1024 segs, 4 per thread
        #pragma unroll
        for (int j = 0; j < 4; ++j) {
            int idx = j * 256 + tid;
            int row = idx >> 3, sg = idx & 7;
            const __half* src = g_Eh + ((size_t)row * CD + sg * 8);
            cp16(base + SM_E + row * ET_STRIDE + sg * 16, src);
        }
        CP_COMMIT();
    }

    int g = lane >> 2;
    float qsq_r[4];
    #pragma unroll
    for (int s = 0; s < 4; ++s)
        qsq_r[s] = __ldg(g_qsq + mb * 128 + wm * 32 + g + s * 8);

    uint32_t aQ = base + (uint32_t)(wm * 32 + (lane & 15)) * QT_STRIDE + ((lane >> 4) << 4);
    uint32_t bE0 = base + SM_E + (uint32_t)(wn * 64 + (lane & 15)) * ET_STRIDE + ((lane >> 4) << 4);

    float acc[2][8][4];
    #pragma unroll
    for (int mf = 0; mf < 2; ++mf)
        #pragma unroll
        for (int nf = 0; nf < 8; ++nf)
            #pragma unroll
            for (int u = 0; u < 4; ++u) acc[mf][nf][u] = 0.0f;

    float bv[4][4];
    int   bi[4][4];
    #pragma unroll
    for (int s = 0; s < 4; ++s)
        #pragma unroll
        for (int j = 0; j < 4; ++j) { bv[s][j] = 3.4e38f; bi[s][j] = 0x7FFFFFFF; }

    int cn_base = wn * 64 + 2 * (lane & 3);

    for (int it = 0; it < NTILES * 4; ++it) {
        int t = it >> 2, kc = it & 3, buf = it & 1;

        if (it < NTILES * 4 - 1) {
            int nit = it + 1, tn = nit >> 2, kcn = nit & 3, bufn = nit & 1;
            #pragma unroll
            for (int j = 0; j < 4; ++j) {
                int idx = j * 256 + tid;
                int row = idx >> 3, sg = idx & 7;
                const __half* src = g_Eh + ((size_t)(tn * 128 + row) * CD + kcn * 64 + sg * 8);
                cp16(base + SM_E + bufn * ET_BYTES + row * ET_STRIDE + sg * 16, src);
            }
            CP_COMMIT();
            CP_WAIT(1);
        } else {
            CP_WAIT(0);
        }
        __syncthreads();

        uint32_t bE = bE0 + buf * ET_BYTES;
        #pragma unroll
        for (int ks = 0; ks < 4; ++ks) {
            int kb = kc * 128 + ks * 32;
            uint32_t ah[2][4];
            ldsm4(ah[0], aQ + kb);
            ldsm4(ah[1], aQ + 16 * QT_STRIDE + kb);
            uint32_t bh[4][4];
            #pragma unroll
            for (int np = 0; np < 4; ++np)
                ldsm4(bh[np], bE + np * 16 * ET_STRIDE + ks * 32);
            #pragma unroll
            for (int mf = 0; mf < 2; ++mf) {
                #pragma unroll
                for (int np = 0; np < 4; ++np) {
                    mma16816(acc[mf][np * 2],     ah[mf], bh[np][0], bh[np][2]);
                    mma16816(acc[mf][np * 2 + 1], ah[mf], bh[np][1], bh[np][3]);
                }
            }
        }

        if (kc == 3) {
            #pragma unroll
            for (int nf = 0; nf < 8; ++nf) {
                int cn = cn_base + nf * 8;
                float2 eq = __ldg((const float2*)(g_esq + t * 128 + cn));
                #pragma unroll
                for (int mf = 0; mf < 2; ++mf) {
                    float* c = acc[mf][nf];
                    float s0 = (qsq_r[mf * 2]     + eq.x) - 2.0f * c[0];
                    float s1 = (qsq_r[mf * 2]     + eq.y) - 2.0f * c[1];
                    float s2 = (qsq_r[mf * 2 + 1] + eq.x) - 2.0f * c[2];
                    float s3 = (qsq_r[mf * 2 + 1] + eq.y) - 2.0f * c[3];
                    int gi = t * 128 + cn;
                    ins4(s0, gi,     bv[mf * 2],     bi[mf * 2]);
                    ins4(s1, gi + 1, bv[mf * 2],     bi[mf * 2]);
                    ins4(s2, gi,     bv[mf * 2 + 1], bi[mf * 2 + 1]);
                    ins4(s3, gi + 1, bv[mf * 2 + 1], bi[mf * 2 + 1]);
                    c[0] = 0.0f; c[1] = 0.0f; c[2] = 0.0f; c[3] = 0.0f;
                }
            }
        }
        __syncthreads();
    }

    // ---- cross-thread top-4 merge over tc lanes (offsets 1,2) ----
    #pragma unroll
    for (int s = 0; s < 4; ++s) {
        #pragma unroll
        for (int off = 1; off <= 2; off <<= 1) {
            float ov[4]; int oi[4];
            #pragma unroll
            for (int j = 0; j < 4; ++j) {
                ov[j] = __shfl_xor_sync(0xffffffffu, bv[s][j], off);
                oi[j] = __shfl_xor_sync(0xffffffffu, bi[s][j], off);
            }
            #pragma unroll
            for (int j = 0; j < 4; ++j) ins4(ov[j], oi[j], bv[s], bi[s]);
        }
    }
    // ---- cross-wn merge via smem ----
    float* rv = (float*)(sm + SM_E);            // [4][256]
    int*   ri = (int*)(sm + SM_E + 4096);       // [4][256]
    if ((lane & 3) == 0) {
        #pragma unroll
        for (int s = 0; s < 4; ++s) {
            int row = wm * 32 + g + s * 8;
            #pragma unroll
            for (int j = 0; j < 4; ++j) {
                rv[j * 256 + wn * 128 + row] = bv[s][j];
                ri[j * 256 + wn * 128 + row] = bi[s][j];
            }
        }
    }
    __syncthreads();
    if (tid < 128) {
        float v[4]; int ix[4];
        #pragma unroll
        for (int j = 0; j < 4; ++j) { v[j] = rv[j * 256 + tid]; ix[j] = ri[j * 256 + tid]; }
        #pragma unroll
        for (int j = 0; j < 4; ++j)
            ins4(rv[j * 256 + 128 + tid], ri[j * 256 + 128 + tid], v, ix);
        int4 c;
        c.x = ix[0]; c.y = ix[1]; c.z = ix[2]; c.w = ix[3];
        g_cand[mb * 128 + tid] = c;
    }
}

// ---------------------------------------------------------------------------
// Kernel B2: rescore top-4 with bit-exact sequential fp32 FMA (ascending k),
// candidates processed in ascending index order; strict < (first wins ties).
// ---------------------------------------------------------------------------
__global__ void rescore_kernel(const float* __restrict__ Q, const float* __restrict__ E) {
    int q = blockIdx.x * 256 + threadIdx.x;
    int4 c4 = g_cand[q];
    int id[4] = {c4.x, c4.y, c4.z, c4.w};
    // sort 4 ascending (network)
    #define SW(a, b) { if (id[a] > id[b]) { int t = id[a]; id[a] = id[b]; id[b] = t; } }
    SW(0, 1) SW(2, 3) SW(0, 2) SW(1, 3) SW(1, 2)
    #undef SW

    const float* qp = Q + (size_t)q * CD;
    float qsq = 0.0f;
    #pragma unroll 4
    for (int k = 0; k < CD; ++k) {
        float qk = qp[k];
        qsq = fmaf(qk, qk, qsq);
    }
    float best = 3.4e38f;
    int bidx = -1;
    for (int j = 0; j < 4; ++j) {
        if (j > 0 && id[j] == id[j - 1]) continue;
        const float* e = E + (size_t)id[j] * CD;
        float es = 0.0f, d = 0.0f;
        #pragma unroll 4
        for (int k = 0; k < CD; ++k) {
            float ek = e[k];
            es = fmaf(ek, ek, es);
            d  = fmaf(qp[k], ek, d);
        }
        float s = (qsq + es) - 2.0f * d;
        if (s < best) { best = s; bidx = id[j]; }
    }
    g_argmin[q] = bidx;
}

// ---------------------------------------------------------------------------
// Kernel C: gather quantized + index output + loss sum
// ---------------------------------------------------------------------------
__global__ void gather_kernel(const float* __restrict__ Q, const float* __restrict__ E,
                              float* __restrict__ out) {
    int q = blockIdx.x * 4 + (threadIdx.x >> 6);
    int lane = threadIdx.x & 63;
    int idx = g_argmin[q];

    float4 qv = ((const float4*)Q)[q * (CD / 4) + lane];
    float4 ev = ((const float4*)E)[(size_t)idx * (CD / 4) + lane];

    float dx = ev.x - qv.x, dy = ev.y - qv.y, dz = ev.z - qv.z, dw = ev.w - qv.w;
    float4 o;
    o.x = qv.x + dx; o.y = qv.y + dy; o.z = qv.z + dz; o.w = qv.w + dw;
    ((float4*)(out + NQ))[q * (CD / 4) + lane] = o;
    if (lane == 0) out[q] = (float)idx;

    float d2 = dx * dx + dy * dy + dz * dz + dw * dw;
    #pragma unroll
    for (int off = 16; off > 0; off >>= 1)
        d2 += __shfl_down_sync(0xffffffffu, d2, off);

    __shared__ float ws[8];
    int w = threadIdx.x >> 5;
    if ((threadIdx.x & 31) == 0) ws[w] = d2;
    __syncthreads();
    if (threadIdx.x == 0) {
        float s = 0.0f;
        #pragma unroll
        for (int i = 0; i < 8; ++i) s += ws[i];
        atomicAdd(&g_loss, s);
    }
}

__global__ void loss_kernel(float* __restrict__ out) {
    out[NQ + NQ * CD] = 1.25f * g_loss * (1.0f / (float)(NQ * CD));
}

// ---------------------------------------------------------------------------
extern "C" void kernel_launch(void* const* d_in, const int* in_sizes, int n_in,
                              void* d_out, int out_size) {
    const float* Q = (const float*)d_in[0];
    const float* E = (const float*)d_in[1];
    if (n_in >= 2 && in_sizes[0] == NC * CD && in_sizes[1] == NQ * CD) {
        const float* t = Q; Q = E; E = t;
    }
    float* out = (float*)d_out;

    cudaFuncSetAttribute(argmin_mma_kernel, cudaFuncAttributeMaxDynamicSharedMemorySize,
                         SM_TOTAL);

    prep_kernel<<<(NC + NQ) / 256, 256>>>(Q, E);
    argmin_mma_kernel<<<NBLK, 256, SM_TOTAL>>>();
    rescore_kernel<<<NQ / 256, 256>>>(Q, E);
    gather_kernel<<<NQ / 4, 256>>>(Q, E, out);
    loss_kernel<<<1, 1>>>(out);
}

// round 14
// speedup vs baseline: 3.0225x; 1.0735x over previous
#include <cuda_runtime.h>
#include <cuda_fp16.h>
#include <cstdint>

#define NQ 16384
#define NC 8192
#define CD 256
#define BM 128
#define BN 128
#define NTILES (NC / BN)      // 64
#define NBLK (NQ / BM)        // 128

// ---- device scratch ----
__device__ __half g_Qh[NQ * CD];   // fp16 operands, row-major
__device__ __half g_Eh[NC * CD];
__device__ float g_qsq[NQ];
__device__ float g_esq[NC];
__device__ int4  g_cand[NQ];       // top-4 candidate indices per query
__device__ int   g_argmin[NQ];
__device__ float g_loss;

// ---- SMEM layout (bytes) ----
// Q: 128 rows x 528B (256 half + 8 pad) = 67584
// E: 2 bufs x 128 rows x 528B          = 135168  (full K=256 tile per buffer)
#define QT_STRIDE 528
#define ET_STRIDE 528
#define ET_BYTES  67584               // 128*528, one full tile
#define SM_E      67584
#define SM_TOTAL  202752              // 67584 + 2*67584

__device__ __forceinline__ uint32_t smem_u32(const void* p) {
    uint32_t a;
    asm("{ .reg .u64 t; cvta.to.shared.u64 t, %1; cvt.u32.u64 %0, t; }" : "=r"(a) : "l"(p));
    return a;
}

__device__ __forceinline__ void cp16(uint32_t dst, const void* src) {
    asm volatile("cp.async.cg.shared.global [%0], [%1], 16;" :: "r"(dst), "l"(src) : "memory");
}
#define CP_COMMIT() asm volatile("cp.async.commit_group;" ::: "memory")
#define CP_WAIT(N)  asm volatile("cp.async.wait_group %0;" :: "n"(N) : "memory")

__device__ __forceinline__ void ldsm4(uint32_t* r, uint32_t addr) {
    asm volatile("ldmatrix.sync.aligned.m8n8.x4.shared.b16 {%0,%1,%2,%3}, [%4];"
                 : "=r"(r[0]), "=r"(r[1]), "=r"(r[2]), "=r"(r[3]) : "r"(addr));
}

__device__ __forceinline__ void mma16816(float* c, const uint32_t* a, uint32_t b0, uint32_t b1) {
    asm volatile(
        "mma.sync.aligned.m16n8k16.row.col.f32.f16.f16.f32 "
        "{%0,%1,%2,%3}, {%4,%5,%6,%7}, {%8,%9}, {%0,%1,%2,%3};"
        : "+f"(c[0]), "+f"(c[1]), "+f"(c[2]), "+f"(c[3])
        : "r"(a[0]), "r"(a[1]), "r"(a[2]), "r"(a[3]), "r"(b0), "r"(b1));
}

// sorted top-4 insert (ascending), (value,index) lexicographic
__device__ __forceinline__ void ins4(float v, int i, float* bv, int* bi) {
    if (v < bv[3] || (v == bv[3] && i < bi[3])) {
        if (v < bv[1] || (v == bv[1] && i < bi[1])) {
            bv[3] = bv[2]; bi[3] = bi[2]; bv[2] = bv[1]; bi[2] = bi[1];
            if (v < bv[0] || (v == bv[0] && i < bi[0])) {
                bv[1] = bv[0]; bi[1] = bi[0]; bv[0] = v; bi[0] = i;
            } else { bv[1] = v; bi[1] = i; }
        } else {
            if (v < bv[2] || (v == bv[2] && i < bi[2])) {
                bv[3] = bv[2]; bi[3] = bi[2]; bv[2] = v; bi[2] = i;
            } else { bv[3] = v; bi[3] = i; }
        }
    }
}

// ---------------------------------------------------------------------------
// Kernel A: fp16 convert (row-major) + fp32 qsq/esq.  One thread per row.
// ---------------------------------------------------------------------------
__global__ void prep_kernel(const float* __restrict__ Q, const float* __restrict__ E) {
    int idx = blockIdx.x * blockDim.x + threadIdx.x;
    if (idx == 0) g_loss = 0.0f;
    if (idx >= NC + NQ) return;

    const float* src;
    __half* d1;
    if (idx < NC) { src = E + (size_t)idx * CD; d1 = g_Eh + (size_t)idx * CD; }
    else { int q = idx - NC; src = Q + (size_t)q * CD; d1 = g_Qh + (size_t)q * CD; }

    float s = 0.0f;
    const float4* s4 = (const float4*)src;
    #pragma unroll 4
    for (int k4 = 0; k4 < CD / 4; ++k4) {
        float4 v = s4[k4];
        s += v.x * v.x + v.y * v.y + v.z * v.z + v.w * v.w;
        int k = k4 * 4;
        *(__half2*)(d1 + k)     = __floats2half2_rn(v.x, v.y);
        *(__half2*)(d1 + k + 2) = __floats2half2_rn(v.z, v.w);
    }
    if (idx < NC) g_esq[idx] = s;
    else          g_qsq[idx - NC] = s;
}

// ---------------------------------------------------------------------------
// Kernel B: single-pass fp16 mma.sync GEMM + fused top-4 candidate search.
// Full-K (256) E tiles per iteration: 64 iterations, one sync pair each.
// ---------------------------------------------------------------------------
__global__ void __launch_bounds__(256, 1) argmin_mma_kernel() {
    extern __shared__ char sm[];
    uint32_t base = smem_u32(sm);
    int tid = threadIdx.x;
    int lane = tid & 31;
    int wm = (tid >> 5) & 3;      // warp M position (32 rows)
    int wn = tid >> 7;            // warp N position (64 cols)
    int mb = blockIdx.x;

    // ---- stage Q tile + first full E tile via cp.async ----
    {
        #pragma unroll
        for (int j = 0; j < 16; ++j) {
            int s = j * 256 + tid;          // 4096 16B segs
            int r = s >> 5;
            int seg = s & 31;
            const __half* src = g_Qh + ((size_t)(mb * 128 + r) * CD + seg * 8);
            cp16(base + r * QT_STRIDE + seg * 16, src);
        }
        #pragma unroll
        for (int j = 0; j < 16; ++j) {
            int s = j * 256 + tid;
            int r = s >> 5;
            int seg = s & 31;
            const __half* src = g_Eh + ((size_t)r * CD + seg * 8);
            cp16(base + SM_E + r * ET_STRIDE + seg * 16, src);
        }
        CP_COMMIT();
    }

    int g = lane >> 2;
    float qsq_r[4];
    #pragma unroll
    for (int s = 0; s < 4; ++s)
        qsq_r[s] = __ldg(g_qsq + mb * 128 + wm * 32 + g + s * 8);

    uint32_t aQ = base + (uint32_t)(wm * 32 + (lane & 15)) * QT_STRIDE + ((lane >> 4) << 4);
    uint32_t bE0 = base + SM_E + (uint32_t)(wn * 64 + (lane & 15)) * ET_STRIDE + ((lane >> 4) << 4);

    float acc[2][8][4];
    #pragma unroll
    for (int mf = 0; mf < 2; ++mf)
        #pragma unroll
        for (int nf = 0; nf < 8; ++nf)
            #pragma unroll
            for (int u = 0; u < 4; ++u) acc[mf][nf][u] = 0.0f;

    float bv[4][4];
    int   bi[4][4];
    #pragma unroll
    for (int s = 0; s < 4; ++s)
        #pragma unroll
        for (int j = 0; j < 4; ++j) { bv[s][j] = 3.4e38f; bi[s][j] = 0x7FFFFFFF; }

    int cn_base = wn * 64 + 2 * (lane & 3);

    for (int t = 0; t < NTILES; ++t) {
        int buf = t & 1;

        if (t < NTILES - 1) {
            int bufn = (t + 1) & 1;
            #pragma unroll
            for (int j = 0; j < 16; ++j) {
                int s = j * 256 + tid;
                int r = s >> 5;
                int seg = s & 31;
                const __half* src = g_Eh + ((size_t)((t + 1) * 128 + r) * CD + seg * 8);
                cp16(base + SM_E + bufn * ET_BYTES + r * ET_STRIDE + seg * 16, src);
            }
            CP_COMMIT();
            CP_WAIT(1);
        } else {
            CP_WAIT(0);
        }
        __syncthreads();

        uint32_t bE = bE0 + buf * ET_BYTES;
        #pragma unroll
        for (int ks = 0; ks < 16; ++ks) {
            int kb = ks * 32;
            uint32_t ah[2][4];
            ldsm4(ah[0], aQ + kb);
            ldsm4(ah[1], aQ + 16 * QT_STRIDE + kb);
            uint32_t bh[4][4];
            #pragma unroll
            for (int np = 0; np < 4; ++np)
                ldsm4(bh[np], bE + np * 16 * ET_STRIDE + kb);
            #pragma unroll
            for (int mf = 0; mf < 2; ++mf) {
                #pragma unroll
                for (int np = 0; np < 4; ++np) {
                    mma16816(acc[mf][np * 2],     ah[mf], bh[np][0], bh[np][2]);
                    mma16816(acc[mf][np * 2 + 1], ah[mf], bh[np][1], bh[np][3]);
                }
            }
        }

        // per-tile epilogue: distances + running top-4, ascending col order
        #pragma unroll
        for (int nf = 0; nf < 8; ++nf) {
            int cn = cn_base + nf * 8;
            float2 eq = __ldg((const float2*)(g_esq + t * 128 + cn));
            #pragma unroll
            for (int mf = 0; mf < 2; ++mf) {
                float* c = acc[mf][nf];
                float s0 = (qsq_r[mf * 2]     + eq.x) - 2.0f * c[0];
                float s1 = (qsq_r[mf * 2]     + eq.y) - 2.0f * c[1];
                float s2 = (qsq_r[mf * 2 + 1] + eq.x) - 2.0f * c[2];
                float s3 = (qsq_r[mf * 2 + 1] + eq.y) - 2.0f * c[3];
                int gi = t * 128 + cn;
                ins4(s0, gi,     bv[mf * 2],     bi[mf * 2]);
                ins4(s1, gi + 1, bv[mf * 2],     bi[mf * 2]);
                ins4(s2, gi,     bv[mf * 2 + 1], bi[mf * 2 + 1]);
                ins4(s3, gi + 1, bv[mf * 2 + 1], bi[mf * 2 + 1]);
                c[0] = 0.0f; c[1] = 0.0f; c[2] = 0.0f; c[3] = 0.0f;
            }
        }
        __syncthreads();
    }

    // ---- cross-thread top-4 merge over tc lanes (offsets 1,2) ----
    #pragma unroll
    for (int s = 0; s < 4; ++s) {
        #pragma unroll
        for (int off = 1; off <= 2; off <<= 1) {
            float ov[4]; int oi[4];
            #pragma unroll
            for (int j = 0; j < 4; ++j) {
                ov[j] = __shfl_xor_sync(0xffffffffu, bv[s][j], off);
                oi[j] = __shfl_xor_sync(0xffffffffu, bi[s][j], off);
            }
            #pragma unroll
            for (int j = 0; j < 4; ++j) ins4(ov[j], oi[j], bv[s], bi[s]);
        }
    }
    // ---- cross-wn merge via smem ----
    float* rv = (float*)(sm + SM_E);            // [4][256]
    int*   ri = (int*)(sm + SM_E + 4096);       // [4][256]
    if ((lane & 3) == 0) {
        #pragma unroll
        for (int s = 0; s < 4; ++s) {
            int row = wm * 32 + g + s * 8;
            #pragma unroll
            for (int j = 0; j < 4; ++j) {
                rv[j * 256 + wn * 128 + row] = bv[s][j];
                ri[j * 256 + wn * 128 + row] = bi[s][j];
            }
        }
    }
    __syncthreads();
    if (tid < 128) {
        float v[4]; int ix[4];
        #pragma unroll
        for (int j = 0; j < 4; ++j) { v[j] = rv[j * 256 + tid]; ix[j] = ri[j * 256 + tid]; }
        #pragma unroll
        for (int j = 0; j < 4; ++j)
            ins4(rv[j * 256 + 128 + tid], ri[j * 256 + 128 + tid], v, ix);
        int4 c;
        c.x = ix[0]; c.y = ix[1]; c.z = ix[2]; c.w = ix[3];
        g_cand[mb * 128 + tid] = c;
    }
}

// ---------------------------------------------------------------------------
// Kernel B2: rescore top-4 with bit-exact sequential fp32 FMA (ascending k),
// candidates processed in ascending index order; strict < (first wins ties).
// ---------------------------------------------------------------------------
__global__ void rescore_kernel(const float* __restrict__ Q, const float* __restrict__ E) {
    int q = blockIdx.x * 256 + threadIdx.x;
    int4 c4 = g_cand[q];
    int id[4] = {c4.x, c4.y, c4.z, c4.w};
    #define SW(a, b) { if (id[a] > id[b]) { int t = id[a]; id[a] = id[b]; id[b] = t; } }
    SW(0, 1) SW(2, 3) SW(0, 2) SW(1, 3) SW(1, 2)
    #undef SW

    const float* qp = Q + (size_t)q * CD;
    float qsq = 0.0f;
    #pragma unroll 4
    for (int k = 0; k < CD; ++k) {
        float qk = qp[k];
        qsq = fmaf(qk, qk, qsq);
    }
    float best = 3.4e38f;
    int bidx = -1;
    for (int j = 0; j < 4; ++j) {
        if (j > 0 && id[j] == id[j - 1]) continue;
        const float* e = E + (size_t)id[j] * CD;
        float es = 0.0f, d = 0.0f;
        #pragma unroll 4
        for (int k = 0; k < CD; ++k) {
            float ek = e[k];
            es = fmaf(ek, ek, es);
            d  = fmaf(qp[k], ek, d);
        }
        float s = (qsq + es) - 2.0f * d;
        if (s < best) { best = s; bidx = id[j]; }
    }
    g_argmin[q] = bidx;
}

// ---------------------------------------------------------------------------
// Kernel C: gather quantized + index output + loss sum
// ---------------------------------------------------------------------------
__global__ void gather_kernel(const float* __restrict__ Q, const float* __restrict__ E,
                              float* __restrict__ out) {
    int q = blockIdx.x * 4 + (threadIdx.x >> 6);
    int lane = threadIdx.x & 63;
    int idx = g_argmin[q];

    float4 qv = ((const float4*)Q)[q * (CD / 4) + lane];
    float4 ev = ((const float4*)E)[(size_t)idx * (CD / 4) + lane];

    float dx = ev.x - qv.x, dy = ev.y - qv.y, dz = ev.z - qv.z, dw = ev.w - qv.w;
    float4 o;
    o.x = qv.x + dx; o.y = qv.y + dy; o.z = qv.z + dz; o.w = qv.w + dw;
    ((float4*)(out + NQ))[q * (CD / 4) + lane] = o;
    if (lane == 0) out[q] = (float)idx;

    float d2 = dx * dx + dy * dy + dz * dz + dw * dw;
    #pragma unroll
    for (int off = 16; off > 0; off >>= 1)
        d2 += __shfl_down_sync(0xffffffffu, d2, off);

    __shared__ float ws[8];
    int w = threadIdx.x >> 5;
    if ((threadIdx.x & 31) == 0) ws[w] = d2;
    __syncthreads();
    if (threadIdx.x == 0) {
        float s = 0.0f;
        #pragma unroll
        for (int i = 0; i < 8; ++i) s += ws[i];
        atomicAdd(&g_loss, s);
    }
}

__global__ void loss_kernel(float* __restrict__ out) {
    out[NQ + NQ * CD] = 1.25f * g_loss * (1.0f / (float)(NQ * CD));
}

// ---------------------------------------------------------------------------
extern "C" void kernel_launch(void* const* d_in, const int* in_sizes, int n_in,
                              void* d_out, int out_size) {
    const float* Q = (const float*)d_in[0];
    const float* E = (const float*)d_in[1];
    if (n_in >= 2 && in_sizes[0] == NC * CD && in_sizes[1] == NQ * CD) {
        const float* t = Q; Q = E; E = t;
    }
    float* out = (float*)d_out;

    cudaFuncSetAttribute(argmin_mma_kernel, cudaFuncAttributeMaxDynamicSharedMemorySize,
                         SM_TOTAL);

    prep_kernel<<<(NC + NQ) / 256, 256>>>(Q, E);
    argmin_mma_kernel<<<NBLK, 256, SM_TOTAL>>>();
    rescore_kernel<<<NQ / 256, 256>>>(Q, E);
    gather_kernel<<<NQ / 4, 256>>>(Q, E, out);
    loss_kernel<<<1, 1>>>(out);
}